// round 7
// baseline (speedup 1.0000x reference)
#include <cuda_runtime.h>
#include <cstdint>

// Problem constants: x(8,1024,256), adj(8,1024,1024), W(256,256), a(1,4,128)
#define Bb    8
#define Nn    1024
#define Cc    256
#define Hh    4
#define Dd    64
#define Mrows (Bb*Nn)   // 8192 token rows
#define HD    (Hh*Dd)   // 256

typedef unsigned long long u64;

// Scratch (static device arrays: no allocation allowed)
__device__ __align__(16) static float g_Wx[Mrows*HD];   // 8.4 MB
__device__ __align__(16) static float g_ei[Mrows*Hh];
__device__ __align__(16) static float g_ej[Mrows*Hh];

// ---------------- packed f32x2 helpers ----------------
__device__ __forceinline__ u64 pk2(float v) {
    u64 r; unsigned u = __float_as_uint(v);
    asm("mov.b64 %0, {%1, %1};" : "=l"(r) : "r"(u));
    return r;
}
__device__ __forceinline__ void fma2(u64& c, u64 a, u64 b) {
    asm("fma.rn.f32x2 %0, %1, %2, %3;" : "=l"(c) : "l"(a), "l"(b), "l"(c));
}

// ---------------- Kernel A: Wx = x @ W, fused e_i/e_j ----------------
// BM=128, BN=64 (== one head), BK=16, 256 threads, double-buffered pipeline.
#define BM 128
#define BN 64
#define BK 16

__global__ __launch_bounds__(256) void gemm_eij_kernel(const float* __restrict__ x,
                                                       const float* __restrict__ W,
                                                       const float* __restrict__ a) {
    __shared__ __align__(16) float As[2][BK][BM + 2];  // transposed A, padded
    __shared__ __align__(16) u64   Bs[2][BK][BN];      // B pre-packed as f32x2 pairs
    __shared__ float s_ai[Dd], s_aj[Dd];

    const int t  = threadIdx.x;
    const int bm = blockIdx.x * BM;
    const int h  = blockIdx.y;         // head: block covers cols [h*64, h*64+64)
    const int bn = h * BN;

    if (t < Dd) { s_ai[t] = a[h * 2 * Dd + t]; s_aj[t] = a[h * 2 * Dd + Dd + t]; }

    const int tx   = t & 15;     // 4 cols each
    const int ty   = t >> 4;     // 8 rows each
    const int lrow = t >> 1;     // A-loader row 0..127
    const int lk   = (t & 1) * 8;
    const int bkr  = t >> 4;     // B-loader k-row 0..15
    const int bnc  = (t & 15) * 4;

    const float* asrc = x + (size_t)(bm + lrow) * Cc + lk;
    const float* bsrc = W + (size_t)bkr * HD + bn + bnc;

    // prologue: load tile k0=0 and stage to buffer 0
    {
        float4 v0 = *reinterpret_cast<const float4*>(asrc);
        float4 v1 = *reinterpret_cast<const float4*>(asrc + 4);
        float4 bv = *reinterpret_cast<const float4*>(bsrc);
        As[0][lk+0][lrow]=v0.x; As[0][lk+1][lrow]=v0.y; As[0][lk+2][lrow]=v0.z; As[0][lk+3][lrow]=v0.w;
        As[0][lk+4][lrow]=v1.x; As[0][lk+5][lrow]=v1.y; As[0][lk+6][lrow]=v1.z; As[0][lk+7][lrow]=v1.w;
        Bs[0][bkr][bnc+0]=pk2(bv.x); Bs[0][bkr][bnc+1]=pk2(bv.y);
        Bs[0][bkr][bnc+2]=pk2(bv.z); Bs[0][bkr][bnc+3]=pk2(bv.w);
    }
    __syncthreads();

    u64 acc[4][4];
#pragma unroll
    for (int i = 0; i < 4; i++)
#pragma unroll
        for (int j = 0; j < 4; j++) acc[i][j] = 0ull;

    int p = 0;
    for (int k0 = 0; k0 < Cc; k0 += BK) {
        const bool more = (k0 + BK) < Cc;
        float4 na0, na1, nb;
        if (more) {  // prefetch next tile into registers (overlaps with compute below)
            na0 = *reinterpret_cast<const float4*>(asrc + k0 + BK);
            na1 = *reinterpret_cast<const float4*>(asrc + k0 + BK + 4);
            nb  = *reinterpret_cast<const float4*>(bsrc + (size_t)(k0 + BK) * HD);
        }
#pragma unroll
        for (int kk = 0; kk < BK; kk++) {
            const float* ap = &As[p][kk][ty * 8];
            u64 ar0 = *reinterpret_cast<const u64*>(ap + 0);
            u64 ar1 = *reinterpret_cast<const u64*>(ap + 2);
            u64 ar2 = *reinterpret_cast<const u64*>(ap + 4);
            u64 ar3 = *reinterpret_cast<const u64*>(ap + 6);
            const u64* bp = &Bs[p][kk][tx * 4];
            u64 b0 = bp[0], b1 = bp[1], b2 = bp[2], b3 = bp[3];
            fma2(acc[0][0],ar0,b0); fma2(acc[0][1],ar0,b1); fma2(acc[0][2],ar0,b2); fma2(acc[0][3],ar0,b3);
            fma2(acc[1][0],ar1,b0); fma2(acc[1][1],ar1,b1); fma2(acc[1][2],ar1,b2); fma2(acc[1][3],ar1,b3);
            fma2(acc[2][0],ar2,b0); fma2(acc[2][1],ar2,b1); fma2(acc[2][2],ar2,b2); fma2(acc[2][3],ar2,b3);
            fma2(acc[3][0],ar3,b0); fma2(acc[3][1],ar3,b1); fma2(acc[3][2],ar3,b2); fma2(acc[3][3],ar3,b3);
        }
        if (more) {
            const int q = p ^ 1;
            As[q][lk+0][lrow]=na0.x; As[q][lk+1][lrow]=na0.y; As[q][lk+2][lrow]=na0.z; As[q][lk+3][lrow]=na0.w;
            As[q][lk+4][lrow]=na1.x; As[q][lk+5][lrow]=na1.y; As[q][lk+6][lrow]=na1.z; As[q][lk+7][lrow]=na1.w;
            Bs[q][bkr][bnc+0]=pk2(nb.x); Bs[q][bkr][bnc+1]=pk2(nb.y);
            Bs[q][bkr][bnc+2]=pk2(nb.z); Bs[q][bkr][bnc+3]=pk2(nb.w);
        }
        __syncthreads();
        p ^= 1;
    }

    // Epilogue: write Wx and fused per-head e_i/e_j partials
    float pi[4][2], pj[4][2];
#pragma unroll
    for (int rp = 0; rp < 4; rp++) {
        const int r = bm + ty * 8 + rp * 2;
        float six = 0.f, siy = 0.f, sjx = 0.f, sjy = 0.f;
#pragma unroll
        for (int q = 0; q < 4; q++) {
            float2 v = *reinterpret_cast<float2*>(&acc[rp][q]);
            const int d = tx * 4 + q;
            g_Wx[(size_t)r * HD + bn + d]       = v.x;
            g_Wx[(size_t)(r + 1) * HD + bn + d] = v.y;
            six += v.x * s_ai[d]; sjx += v.x * s_aj[d];
            siy += v.y * s_ai[d]; sjy += v.y * s_aj[d];
        }
        pi[rp][0] = six; pi[rp][1] = siy;
        pj[rp][0] = sjx; pj[rp][1] = sjy;
    }
    // reduce across the 16 tx lanes (stays within each half-warp)
#pragma unroll
    for (int rp = 0; rp < 4; rp++) {
#pragma unroll
        for (int o = 1; o < 16; o <<= 1) {
            pi[rp][0] += __shfl_xor_sync(0xffffffffu, pi[rp][0], o);
            pi[rp][1] += __shfl_xor_sync(0xffffffffu, pi[rp][1], o);
            pj[rp][0] += __shfl_xor_sync(0xffffffffu, pj[rp][0], o);
            pj[rp][1] += __shfl_xor_sync(0xffffffffu, pj[rp][1], o);
        }
    }
    if (tx == 0) {
#pragma unroll
        for (int rp = 0; rp < 4; rp++) {
            const int r = bm + ty * 8 + rp * 2;
            g_ei[r * Hh + h]       = pi[rp][0];
            g_ei[(r + 1) * Hh + h] = pi[rp][1];
            g_ej[r * Hh + h]       = pj[rp][0];
            g_ej[(r + 1) * Hh + h] = pj[rp][1];
        }
    }
}

// ---------------- Kernel B: sparse masked softmax + aggregation ----------------
// One block per (b, n). Deterministic compaction; exp without max subtraction
// (args bounded ~|8|, safe in fp32); gather with MLP=8.
__global__ __launch_bounds__(256) void attn_kernel(const float* __restrict__ adj,
                                                   float* __restrict__ out) {
    __shared__ int   s_idx[Nn];
    __shared__ __align__(16) float s_e[Nn * Hh];
    __shared__ int   s_wcnt[8];
    __shared__ float s_red[8 * Hh];
    __shared__ float s_ei[Hh];

    const int t    = threadIdx.x;
    const int bid  = blockIdx.x;        // = b*1024 + n
    const int b    = bid >> 10;
    const int n    = bid & (Nn - 1);
    const int lane = t & 31;
    const int w    = t >> 5;

    if (t < Hh) s_ei[t] = g_ei[bid * Hh + t];

    // --- Phase 1: compact neighbor list (adj!=0 || j==n), sorted, no atomics ---
    const float4 av = reinterpret_cast<const float4*>(adj + (size_t)bid * Nn)[t];
    const int j0 = 4 * t;
    const int p0 = (av.x != 0.f) | (j0 == n);
    const int p1 = (av.y != 0.f) | (j0 + 1 == n);
    const int p2 = (av.z != 0.f) | (j0 + 2 == n);
    const int p3 = (av.w != 0.f) | (j0 + 3 == n);
    const int cnt = p0 + p1 + p2 + p3;
    int incl = cnt;
#pragma unroll
    for (int o = 1; o < 32; o <<= 1) {
        int v = __shfl_up_sync(0xffffffffu, incl, o);
        if (lane >= o) incl += v;
    }
    if (lane == 31) s_wcnt[w] = incl;
    __syncthreads();
    int base = 0, total = 0;
#pragma unroll
    for (int ww = 0; ww < 8; ++ww) {
        const int c = s_wcnt[ww];
        total += c;
        if (ww < w) base += c;
    }
    int off = base + incl - cnt;
    if (p0) s_idx[off++] = j0;
    if (p1) s_idx[off++] = j0 + 1;
    if (p2) s_idx[off++] = j0 + 2;
    if (p3) s_idx[off++] = j0 + 3;
    __syncthreads();

    // --- Phase 2: ex = exp(leaky(ei+ej)); per-head sum (no max pass needed) ---
    const float ei0 = s_ei[0], ei1 = s_ei[1], ei2 = s_ei[2], ei3 = s_ei[3];
    float s0 = 0.f, s1 = 0.f, s2 = 0.f, s3 = 0.f;
    for (int k = t; k < total; k += 256) {
        const int j = s_idx[k];
        float4 ej = *reinterpret_cast<const float4*>(g_ej + ((size_t)(b << 10) + j) * Hh);
        float e0 = ei0 + ej.x; e0 = e0 > 0.f ? e0 : 0.2f * e0;
        float e1 = ei1 + ej.y; e1 = e1 > 0.f ? e1 : 0.2f * e1;
        float e2 = ei2 + ej.z; e2 = e2 > 0.f ? e2 : 0.2f * e2;
        float e3 = ei3 + ej.w; e3 = e3 > 0.f ? e3 : 0.2f * e3;
        e0 = __expf(e0); e1 = __expf(e1); e2 = __expf(e2); e3 = __expf(e3);
        reinterpret_cast<float4*>(s_e)[k] = make_float4(e0, e1, e2, e3);
        s0 += e0; s1 += e1; s2 += e2; s3 += e3;
    }
#pragma unroll
    for (int o = 16; o >= 1; o >>= 1) {
        s0 += __shfl_xor_sync(0xffffffffu, s0, o);
        s1 += __shfl_xor_sync(0xffffffffu, s1, o);
        s2 += __shfl_xor_sync(0xffffffffu, s2, o);
        s3 += __shfl_xor_sync(0xffffffffu, s3, o);
    }
    if (lane == 0) { s_red[w*4+0]=s0; s_red[w*4+1]=s1; s_red[w*4+2]=s2; s_red[w*4+3]=s3; }
    __syncthreads();

    // --- Phase 3: out[h,d] = (1/sum_h) * sum_k ex[k,h] * Wx[b, j_k, h*64+d] ---
    const int h = t >> 6;
    const int d = t & 63;
    float gsum = 0.f;
#pragma unroll
    for (int ww = 0; ww < 8; ww++) gsum += s_red[ww*4 + h];

    const float* wxb = g_Wx + (size_t)(b << 10) * HD + h * Dd + d;
    float a0 = 0.f, a1 = 0.f, a2 = 0.f, a3 = 0.f;
    float a4 = 0.f, a5 = 0.f, a6 = 0.f, a7 = 0.f;
    int k = 0;
    for (; k + 8 <= total; k += 8) {
        const int i0 = s_idx[k+0], i1 = s_idx[k+1], i2 = s_idx[k+2], i3 = s_idx[k+3];
        const int i4 = s_idx[k+4], i5 = s_idx[k+5], i6 = s_idx[k+6], i7 = s_idx[k+7];
        const float w0 = s_e[(k+0)*4+h], w1 = s_e[(k+1)*4+h], w2 = s_e[(k+2)*4+h], w3 = s_e[(k+3)*4+h];
        const float w4 = s_e[(k+4)*4+h], w5 = s_e[(k+5)*4+h], w6 = s_e[(k+6)*4+h], w7 = s_e[(k+7)*4+h];
        a0 += w0 * __ldg(wxb + (size_t)i0 * HD);
        a1 += w1 * __ldg(wxb + (size_t)i1 * HD);
        a2 += w2 * __ldg(wxb + (size_t)i2 * HD);
        a3 += w3 * __ldg(wxb + (size_t)i3 * HD);
        a4 += w4 * __ldg(wxb + (size_t)i4 * HD);
        a5 += w5 * __ldg(wxb + (size_t)i5 * HD);
        a6 += w6 * __ldg(wxb + (size_t)i6 * HD);
        a7 += w7 * __ldg(wxb + (size_t)i7 * HD);
    }
    for (; k < total; ++k)
        a0 += s_e[k*4 + h] * __ldg(wxb + (size_t)s_idx[k] * HD);

    const float acc = ((a0 + a1) + (a2 + a3)) + ((a4 + a5) + (a6 + a7));
    out[(size_t)bid * HD + t] = acc / gsum;
}

// ---------------- launch ----------------
extern "C" void kernel_launch(void* const* d_in, const int* in_sizes, int n_in,
                              void* d_out, int out_size) {
    const float* x   = (const float*)d_in[0];  // (8,1024,256)
    const float* adj = (const float*)d_in[1];  // (8,1024,1024)
    const float* W   = (const float*)d_in[2];  // (256,256)
    const float* a   = (const float*)d_in[3];  // (1,4,128)
    float* out = (float*)d_out;                // (8,1024,256)

    (void)in_sizes; (void)n_in; (void)out_size;

    gemm_eij_kernel<<<dim3(Mrows / BM, Hh), 256>>>(x, W, a);
    attn_kernel<<<Mrows, 256>>>(adj, out);
}

// round 10
// speedup vs baseline: 1.2728x; 1.2728x over previous
#include <cuda_runtime.h>
#include <cstdint>

// Problem constants: x(8,1024,256), adj(8,1024,1024), W(256,256), a(1,4,128)
#define Bb    8
#define Nn    1024
#define Cc    256
#define Hh    4
#define Dd    64
#define Mrows (Bb*Nn)   // 8192 token rows
#define HD    (Hh*Dd)   // 256

typedef unsigned long long u64;

// Scratch (static device arrays: no allocation allowed)
__device__ __align__(16) static float g_Wx[Mrows*HD];   // 8.4 MB
__device__ __align__(16) static float g_ei[Mrows*Hh];
__device__ __align__(16) static float g_ej[Mrows*Hh];

// ---------------- packed f32x2 helpers ----------------
__device__ __forceinline__ u64 pk2(float v) {
    u64 r; unsigned u = __float_as_uint(v);
    asm("mov.b64 %0, {%1, %1};" : "=l"(r) : "r"(u));
    return r;
}
__device__ __forceinline__ void fma2(u64& c, u64 a, u64 b) {
    asm("fma.rn.f32x2 %0, %1, %2, %3;" : "=l"(c) : "l"(a), "l"(b), "l"(c));
}

// ---------------- Kernel A: Wx = x @ W, fused e_i/e_j ----------------
// R4-proven single-buffer structure. BM=128, BN=64 (== one head), BK=16.
// B tile pre-packed as f32x2 u64, stored transposed (q*16+tx) so the inner-loop
// reads are conflict-free LDS.64 broadcasts.
#define BM 128
#define BN 64
#define BK 16

__global__ __launch_bounds__(256) void gemm_eij_kernel(const float* __restrict__ x,
                                                       const float* __restrict__ W,
                                                       const float* __restrict__ a) {
    __shared__ __align__(16) float As[BK][BM + 2];  // transposed A, padded
    __shared__ __align__(16) u64   Bs[BK][BN];      // packed pairs, layout [kk][q*16+tx]
    __shared__ float s_ai[Dd], s_aj[Dd];

    const int t  = threadIdx.x;
    const int bm = blockIdx.x * BM;
    const int h  = blockIdx.y;         // head: block covers cols [h*64, h*64+64)
    const int bn = h * BN;

    if (t < Dd) { s_ai[t] = a[h * 2 * Dd + t]; s_aj[t] = a[h * 2 * Dd + Dd + t]; }

    const int tx   = t & 15;     // 4 cols each
    const int ty   = t >> 4;     // 8 rows each
    const int lrow = t >> 1;     // A-loader row 0..127
    const int lk   = (t & 1) * 8;
    const int bkr  = t >> 4;     // B-loader k-row 0..15
    const int btx  = t & 15;     // B-loader col group

    u64 acc[4][4];
#pragma unroll
    for (int i = 0; i < 4; i++)
#pragma unroll
        for (int j = 0; j < 4; j++) acc[i][j] = 0ull;

    for (int k0 = 0; k0 < Cc; k0 += BK) {
        // A tile: 128x16, each thread loads 8 floats, stores transposed
        {
            const float* src = x + (size_t)(bm + lrow) * Cc + k0 + lk;
            float4 v0 = *reinterpret_cast<const float4*>(src);
            float4 v1 = *reinterpret_cast<const float4*>(src + 4);
            As[lk + 0][lrow] = v0.x; As[lk + 1][lrow] = v0.y;
            As[lk + 2][lrow] = v0.z; As[lk + 3][lrow] = v0.w;
            As[lk + 4][lrow] = v1.x; As[lk + 5][lrow] = v1.y;
            As[lk + 6][lrow] = v1.z; As[lk + 7][lrow] = v1.w;
        }
        // B tile: 16x64, pre-packed + transposed: logical col d=btx*4+q -> Bs[kr][q*16+btx]
        {
            float4 v = *reinterpret_cast<const float4*>(W + (size_t)(k0 + bkr) * HD + bn + btx * 4);
            Bs[bkr][0 * 16 + btx] = pk2(v.x);
            Bs[bkr][1 * 16 + btx] = pk2(v.y);
            Bs[bkr][2 * 16 + btx] = pk2(v.z);
            Bs[bkr][3 * 16 + btx] = pk2(v.w);
        }
        __syncthreads();

#pragma unroll
        for (int kk = 0; kk < BK; kk++) {
            const float* ap = &As[kk][ty * 8];
            u64 ar0 = *reinterpret_cast<const u64*>(ap + 0);
            u64 ar1 = *reinterpret_cast<const u64*>(ap + 2);
            u64 ar2 = *reinterpret_cast<const u64*>(ap + 4);
            u64 ar3 = *reinterpret_cast<const u64*>(ap + 6);
            u64 b0 = Bs[kk][0 * 16 + tx];
            u64 b1 = Bs[kk][1 * 16 + tx];
            u64 b2 = Bs[kk][2 * 16 + tx];
            u64 b3 = Bs[kk][3 * 16 + tx];
            fma2(acc[0][0],ar0,b0); fma2(acc[0][1],ar0,b1); fma2(acc[0][2],ar0,b2); fma2(acc[0][3],ar0,b3);
            fma2(acc[1][0],ar1,b0); fma2(acc[1][1],ar1,b1); fma2(acc[1][2],ar1,b2); fma2(acc[1][3],ar1,b3);
            fma2(acc[2][0],ar2,b0); fma2(acc[2][1],ar2,b1); fma2(acc[2][2],ar2,b2); fma2(acc[2][3],ar2,b3);
            fma2(acc[3][0],ar3,b0); fma2(acc[3][1],ar3,b1); fma2(acc[3][2],ar3,b2); fma2(acc[3][3],ar3,b3);
        }
        __syncthreads();
    }

    // Epilogue: write Wx and fused per-head e_i/e_j partials.
    // Note: logical col for acc[.][q] is tx*4+q.
    float pi[4][2], pj[4][2];
#pragma unroll
    for (int rp = 0; rp < 4; rp++) {
        const int r = bm + ty * 8 + rp * 2;
        float six = 0.f, siy = 0.f, sjx = 0.f, sjy = 0.f;
#pragma unroll
        for (int q = 0; q < 4; q++) {
            float2 v = *reinterpret_cast<float2*>(&acc[rp][q]);
            const int d = tx * 4 + q;
            g_Wx[(size_t)r * HD + bn + d]       = v.x;
            g_Wx[(size_t)(r + 1) * HD + bn + d] = v.y;
            six += v.x * s_ai[d]; sjx += v.x * s_aj[d];
            siy += v.y * s_ai[d]; sjy += v.y * s_aj[d];
        }
        pi[rp][0] = six; pi[rp][1] = siy;
        pj[rp][0] = sjx; pj[rp][1] = sjy;
    }
#pragma unroll
    for (int rp = 0; rp < 4; rp++) {
#pragma unroll
        for (int o = 1; o < 16; o <<= 1) {
            pi[rp][0] += __shfl_xor_sync(0xffffffffu, pi[rp][0], o);
            pi[rp][1] += __shfl_xor_sync(0xffffffffu, pi[rp][1], o);
            pj[rp][0] += __shfl_xor_sync(0xffffffffu, pj[rp][0], o);
            pj[rp][1] += __shfl_xor_sync(0xffffffffu, pj[rp][1], o);
        }
    }
    if (tx == 0) {
#pragma unroll
        for (int rp = 0; rp < 4; rp++) {
            const int r = bm + ty * 8 + rp * 2;
            g_ei[r * Hh + h]       = pi[rp][0];
            g_ei[(r + 1) * Hh + h] = pi[rp][1];
            g_ej[r * Hh + h]       = pj[rp][0];
            g_ej[(r + 1) * Hh + h] = pj[rp][1];
        }
    }
}

// ---------------- Kernel B: sparse masked softmax + aggregation ----------------
// One block per (b, n). Deterministic compaction; single-pass exp (logits bounded,
// fp32-safe without max subtraction); gather as float2/fma2 with 128 channel-threads
// x 2 neighbor halves to halve the issue load of the gather.
__global__ __launch_bounds__(256) void attn_kernel(const float* __restrict__ adj,
                                                   float* __restrict__ out) {
    __shared__ int   s_idx[Nn];
    __shared__ __align__(16) float s_w[Nn * Hh];
    __shared__ int   s_wcnt[8];
    __shared__ float s_red[8 * Hh];
    __shared__ float s_ei[Hh];
    __shared__ __align__(16) float2 s_part[128];

    const int t    = threadIdx.x;
    const int bid  = blockIdx.x;        // = b*1024 + n
    const int b    = bid >> 10;
    const int n    = bid & (Nn - 1);
    const int lane = t & 31;
    const int w    = t >> 5;

    if (t < Hh) s_ei[t] = g_ei[bid * Hh + t];

    // --- Phase 1: compact neighbor list (adj!=0 || j==n), sorted, no atomics ---
    const float4 av = reinterpret_cast<const float4*>(adj + (size_t)bid * Nn)[t];
    const int j0 = 4 * t;
    const int p0 = (av.x != 0.f) | (j0 == n);
    const int p1 = (av.y != 0.f) | (j0 + 1 == n);
    const int p2 = (av.z != 0.f) | (j0 + 2 == n);
    const int p3 = (av.w != 0.f) | (j0 + 3 == n);
    const int cnt = p0 + p1 + p2 + p3;
    int incl = cnt;
#pragma unroll
    for (int o = 1; o < 32; o <<= 1) {
        int v = __shfl_up_sync(0xffffffffu, incl, o);
        if (lane >= o) incl += v;
    }
    if (lane == 31) s_wcnt[w] = incl;
    __syncthreads();
    int base = 0, total = 0;
#pragma unroll
    for (int ww = 0; ww < 8; ++ww) {
        const int c = s_wcnt[ww];
        total += c;
        if (ww < w) base += c;
    }
    int off = base + incl - cnt;
    if (p0) s_idx[off++] = j0;
    if (p1) s_idx[off++] = j0 + 1;
    if (p2) s_idx[off++] = j0 + 2;
    if (p3) s_idx[off++] = j0 + 3;
    __syncthreads();

    // --- Phase 2: w = exp(leaky(ei+ej)); per-head sums. Also rewrite s_idx[k]
    //     to the pre-scaled float2 row offset (j*128) for the gather. ---
    const float ei0 = s_ei[0], ei1 = s_ei[1], ei2 = s_ei[2], ei3 = s_ei[3];
    float s0 = 0.f, s1 = 0.f, s2 = 0.f, s3 = 0.f;
    for (int k = t; k < total; k += 256) {
        const int j = s_idx[k];
        float4 ej = *reinterpret_cast<const float4*>(g_ej + ((size_t)(b << 10) + j) * Hh);
        float e0 = ei0 + ej.x; e0 = e0 > 0.f ? e0 : 0.2f * e0;
        float e1 = ei1 + ej.y; e1 = e1 > 0.f ? e1 : 0.2f * e1;
        float e2 = ei2 + ej.z; e2 = e2 > 0.f ? e2 : 0.2f * e2;
        float e3 = ei3 + ej.w; e3 = e3 > 0.f ? e3 : 0.2f * e3;
        e0 = __expf(e0); e1 = __expf(e1); e2 = __expf(e2); e3 = __expf(e3);
        reinterpret_cast<float4*>(s_w)[k] = make_float4(e0, e1, e2, e3);
        s0 += e0; s1 += e1; s2 += e2; s3 += e3;
        s_idx[k] = j << 7;   // float2 units: j * (HD/2)
    }
#pragma unroll
    for (int o = 16; o >= 1; o >>= 1) {
        s0 += __shfl_xor_sync(0xffffffffu, s0, o);
        s1 += __shfl_xor_sync(0xffffffffu, s1, o);
        s2 += __shfl_xor_sync(0xffffffffu, s2, o);
        s3 += __shfl_xor_sync(0xffffffffu, s3, o);
    }
    if (lane == 0) { s_red[w*4+0]=s0; s_red[w*4+1]=s1; s_red[w*4+2]=s2; s_red[w*4+3]=s3; }
    __syncthreads();

    // --- Phase 3: gather. Thread t: half g = t>>7 over neighbors (k = g, g+2, ...),
    //     channel pair c = {2u, 2u+1} with u = t&127. float2 loads + fma2. ---
    const int g = t >> 7;
    const int u = t & 127;
    const int h = u >> 5;

    float gsum = 0.f;
#pragma unroll
    for (int ww = 0; ww < 8; ww++) gsum += s_red[ww*4 + h];

    const float2* basep = reinterpret_cast<const float2*>(g_Wx + ((size_t)(b << 10)) * HD) + u;
    u64 a0 = 0ull, a1 = 0ull, a2 = 0ull, a3 = 0ull;
    int k = g;
    for (; k + 6 < total; k += 8) {
        const int o0 = s_idx[k], o1 = s_idx[k+2], o2 = s_idx[k+4], o3 = s_idx[k+6];
        const u64 w0 = pk2(s_w[(k+0)*4 + h]);
        const u64 w1 = pk2(s_w[(k+2)*4 + h]);
        const u64 w2 = pk2(s_w[(k+4)*4 + h]);
        const u64 w3 = pk2(s_w[(k+6)*4 + h]);
        const u64 r0 = *reinterpret_cast<const u64*>(basep + o0);
        const u64 r1 = *reinterpret_cast<const u64*>(basep + o1);
        const u64 r2 = *reinterpret_cast<const u64*>(basep + o2);
        const u64 r3 = *reinterpret_cast<const u64*>(basep + o3);
        fma2(a0, r0, w0); fma2(a1, r1, w1); fma2(a2, r2, w2); fma2(a3, r3, w3);
    }
    for (; k < total; k += 2) {
        const u64 wv = pk2(s_w[k*4 + h]);
        const u64 rv = *reinterpret_cast<const u64*>(basep + s_idx[k]);
        fma2(a0, rv, wv);
    }
    float2 v0 = *reinterpret_cast<float2*>(&a0);
    float2 v1 = *reinterpret_cast<float2*>(&a1);
    float2 v2 = *reinterpret_cast<float2*>(&a2);
    float2 v3 = *reinterpret_cast<float2*>(&a3);
    float2 part;
    part.x = (v0.x + v1.x) + (v2.x + v3.x);
    part.y = (v0.y + v1.y) + (v2.y + v3.y);

    if (g == 1) s_part[u] = part;
    __syncthreads();
    if (g == 0) {
        const float2 other = s_part[u];
        float2 res;
        res.x = (part.x + other.x) / gsum;
        res.y = (part.y + other.y) / gsum;
        reinterpret_cast<float2*>(out)[(size_t)bid * 128 + u] = res;
    }
}

// ---------------- launch ----------------
extern "C" void kernel_launch(void* const* d_in, const int* in_sizes, int n_in,
                              void* d_out, int out_size) {
    const float* x   = (const float*)d_in[0];  // (8,1024,256)
    const float* adj = (const float*)d_in[1];  // (8,1024,1024)
    const float* W   = (const float*)d_in[2];  // (256,256)
    const float* a   = (const float*)d_in[3];  // (1,4,128)
    float* out = (float*)d_out;                // (8,1024,256)

    (void)in_sizes; (void)n_in; (void)out_size;

    gemm_eij_kernel<<<dim3(Mrows / BM, Hh), 256>>>(x, W, a);
    attn_kernel<<<Mrows, 256>>>(adj, out);
}